// round 1
// baseline (speedup 1.0000x reference)
#include <cuda_runtime.h>
#include <cuda_bf16.h>

// Problem constants
#define B_  4
#define N_  4096
#define D_  1024
#define U_  1024

// Scratch (allowed: __device__ globals, no runtime alloc)
__device__ float g_Q[(size_t)B_ * N_ * U_];
__device__ float g_K[(size_t)B_ * N_ * U_];
__device__ float g_V[(size_t)B_ * N_ * U_];
__device__ float g_S[(size_t)B_ * N_ * N_];

// ---------------------------------------------------------------------------
// Classic SIMT fp32 GEMM: C = alpha * A @ op(B)
//   TB=false: B is [K,N] row-major (NN)
//   TB=true : B is [N,K] row-major, compute A @ B^T (NT)
// 128x128 block tile, BK=16, 256 threads, 8x8 per-thread microtile.
// All dims assumed divisible by tile sizes (true for this problem).
// blockIdx.z = batch; sA/sB/sC are batch strides in elements.
// ---------------------------------------------------------------------------
template <bool TB>
__global__ __launch_bounds__(256, 2)
void sgemm_kernel(const float* __restrict__ A, const float* __restrict__ B,
                  float* __restrict__ C, int M, int N, int K,
                  long long sA, long long sB, long long sC, float alpha)
{
    constexpr int BM = 128, BN = 128, BK = 16, TM = 8, TN = 8;
    __shared__ float As[BK][BM];
    __shared__ float Bs[BK][BN];

    A += (long long)blockIdx.z * sA;
    B += (long long)blockIdx.z * sB;
    C += (long long)blockIdx.z * sC;

    const int tid = threadIdx.x;
    const int tx = tid & 15;        // 0..15  -> col group
    const int ty = tid >> 4;        // 0..15  -> row group
    const int rowBase = blockIdx.y * BM;
    const int colBase = blockIdx.x * BN;

    float acc[TM][TN] = {};

    for (int k0 = 0; k0 < K; k0 += BK) {
        // --- load A tile [BM x BK], store transposed As[k][m] ---
        #pragma unroll
        for (int i = 0; i < 2; i++) {
            int lin = tid + i * 256;          // 0..511 float4 slots
            int r  = lin >> 2;                // row 0..127
            int c4 = (lin & 3) * 4;           // k offset 0,4,8,12
            float4 v = *(const float4*)&A[(long long)(rowBase + r) * K + k0 + c4];
            As[c4 + 0][r] = v.x;
            As[c4 + 1][r] = v.y;
            As[c4 + 2][r] = v.z;
            As[c4 + 3][r] = v.w;
        }
        // --- load B tile ---
        if (TB) {
            // B [N,K] row-major: rows colBase..+128, cols k0..+16 -> Bs[k][n]
            #pragma unroll
            for (int i = 0; i < 2; i++) {
                int lin = tid + i * 256;
                int r  = lin >> 2;            // n 0..127
                int c4 = (lin & 3) * 4;       // k offset
                float4 v = *(const float4*)&B[(long long)(colBase + r) * K + k0 + c4];
                Bs[c4 + 0][r] = v.x;
                Bs[c4 + 1][r] = v.y;
                Bs[c4 + 2][r] = v.z;
                Bs[c4 + 3][r] = v.w;
            }
        } else {
            // B [K,N] row-major: rows k0..+16, cols colBase..+128 -> Bs[k][n]
            #pragma unroll
            for (int i = 0; i < 2; i++) {
                int lin = tid + i * 256;
                int r  = lin >> 5;            // k 0..15
                int c4 = (lin & 31) * 4;      // n offset 0..124
                *(float4*)&Bs[r][c4] =
                    *(const float4*)&B[(long long)(k0 + r) * N + colBase + c4];
            }
        }
        __syncthreads();

        // --- compute ---
        #pragma unroll
        for (int kk = 0; kk < BK; kk++) {
            float a[TM], b[TN];
            *(float4*)&a[0] = *(const float4*)&As[kk][ty * 8];
            *(float4*)&a[4] = *(const float4*)&As[kk][ty * 8 + 4];
            *(float4*)&b[0] = *(const float4*)&Bs[kk][tx * 8];
            *(float4*)&b[4] = *(const float4*)&Bs[kk][tx * 8 + 4];
            #pragma unroll
            for (int i = 0; i < TM; i++)
                #pragma unroll
                for (int j = 0; j < TN; j++)
                    acc[i][j] = fmaf(a[i], b[j], acc[i][j]);
        }
        __syncthreads();
    }

    // --- store ---
    #pragma unroll
    for (int i = 0; i < TM; i++) {
        long long r = rowBase + ty * 8 + i;
        #pragma unroll
        for (int j = 0; j < TN; j += 4) {
            float4 v;
            v.x = acc[i][j + 0] * alpha;
            v.y = acc[i][j + 1] * alpha;
            v.z = acc[i][j + 2] * alpha;
            v.w = acc[i][j + 3] * alpha;
            *(float4*)&C[r * N + colBase + tx * 8 + j] = v;
        }
    }
}

// ---------------------------------------------------------------------------
// Row softmax over S: one block per row of 4096 floats, in place.
// 256 threads, 16 floats per thread held in registers (single HBM round trip).
// ---------------------------------------------------------------------------
__global__ __launch_bounds__(256)
void softmax_rows_kernel(float* __restrict__ S)
{
    float* p = S + (long long)blockIdx.x * N_;
    const int tid = threadIdx.x;

    float4 v[4];
    float mx = -1e30f;
    #pragma unroll
    for (int i = 0; i < 4; i++) {
        v[i] = *(const float4*)&p[(tid + i * 256) * 4];
        mx = fmaxf(mx, fmaxf(fmaxf(v[i].x, v[i].y), fmaxf(v[i].z, v[i].w)));
    }

    __shared__ float redmax[8];
    __shared__ float redsum[8];
    #pragma unroll
    for (int o = 16; o > 0; o >>= 1)
        mx = fmaxf(mx, __shfl_xor_sync(0xFFFFFFFFu, mx, o));
    if ((tid & 31) == 0) redmax[tid >> 5] = mx;
    __syncthreads();
    mx = redmax[0];
    #pragma unroll
    for (int i = 1; i < 8; i++) mx = fmaxf(mx, redmax[i]);

    float sum = 0.f;
    #pragma unroll
    for (int i = 0; i < 4; i++) {
        v[i].x = __expf(v[i].x - mx);
        v[i].y = __expf(v[i].y - mx);
        v[i].z = __expf(v[i].z - mx);
        v[i].w = __expf(v[i].w - mx);
        sum += v[i].x + v[i].y + v[i].z + v[i].w;
    }
    #pragma unroll
    for (int o = 16; o > 0; o >>= 1)
        sum += __shfl_xor_sync(0xFFFFFFFFu, sum, o);
    if ((tid & 31) == 0) redsum[tid >> 5] = sum;
    __syncthreads();
    sum = 0.f;
    #pragma unroll
    for (int i = 0; i < 8; i++) sum += redsum[i];

    const float inv = 1.f / sum;
    #pragma unroll
    for (int i = 0; i < 4; i++) {
        v[i].x *= inv; v[i].y *= inv; v[i].z *= inv; v[i].w *= inv;
        *(float4*)&p[(tid + i * 256) * 4] = v[i];
    }
}

// ---------------------------------------------------------------------------
// Launch
// ---------------------------------------------------------------------------
extern "C" void kernel_launch(void* const* d_in, const int* in_sizes, int n_in,
                              void* d_out, int out_size)
{
    const float* X  = (const float*)d_in[0];   // [B, N, D] -> [16384, 1024]
    const float* WQ = (const float*)d_in[1];   // [D, U]
    const float* WK = (const float*)d_in[2];
    const float* WV = (const float*)d_in[3];
    float* out = (float*)d_out;                // [B, N, U]

    float *Q, *K, *V, *S;
    cudaGetSymbolAddress((void**)&Q, g_Q);
    cudaGetSymbolAddress((void**)&K, g_K);
    cudaGetSymbolAddress((void**)&V, g_V);
    cudaGetSymbolAddress((void**)&S, g_S);

    const int MQKV = B_ * N_;                  // 16384
    const long long strQ = (long long)N_ * U_; // per-batch Q/K/V/out stride
    const long long strS = (long long)N_ * N_; // per-batch scores stride

    dim3 blk(256);

    // 1) Q, K, V projections: [16384,1024] @ [1024,1024]  (NN)
    dim3 gQKV(U_ / 128, MQKV / 128, 1);
    sgemm_kernel<false><<<gQKV, blk>>>(X, WQ, Q, MQKV, U_, D_, 0, 0, 0, 1.0f);
    sgemm_kernel<false><<<gQKV, blk>>>(X, WK, K, MQKV, U_, D_, 0, 0, 0, 1.0f);
    sgemm_kernel<false><<<gQKV, blk>>>(X, WV, V, MQKV, U_, D_, 0, 0, 0, 1.0f);

    // 2) Scores: S_b = (1/32) * Q_b @ K_b^T   [4096,4096], K=1024  (NT, batched)
    dim3 gS(N_ / 128, N_ / 128, B_);
    sgemm_kernel<true><<<gS, blk>>>(Q, K, S, N_, N_, U_,
                                    strQ, strQ, strS, 1.0f / 32.0f);

    // 3) Row softmax in place (16384 rows x 4096)
    softmax_rows_kernel<<<B_ * N_, blk>>>(S);

    // 4) Output: out_b = S_b @ V_b   [4096,1024], K=4096  (NN, batched)
    dim3 gO(U_ / 128, N_ / 128, B_);
    sgemm_kernel<false><<<gO, blk>>>(S, V, out, N_, U_, N_,
                                     strS, strQ, strQ, 1.0f);
}

// round 4
// speedup vs baseline: 1.5993x; 1.5993x over previous
#include <cuda_runtime.h>
#include <cstdint>

// Problem constants
#define B_  4
#define N_  4096
#define D_  1024
#define U_  1024

// Scratch (device globals; no runtime allocation)
__device__ float g_Q [(size_t)B_ * N_ * U_];
__device__ float g_K [(size_t)B_ * N_ * U_];
__device__ float g_VT[(size_t)U_ * B_ * N_];      // V transposed: [U, B*N]
__device__ float g_S [(size_t)B_ * N_ * N_];
__device__ float g_WT[3 * (size_t)D_ * U_];       // WQ^T, WK^T, WV^T (fp32)

// ---------------------------------------------------------------------------
__device__ __forceinline__ float rna_tf32(float x) {
    uint32_t y;
    asm("cvt.rna.tf32.f32 %0, %1;" : "=r"(y) : "f"(x));
    return __uint_as_float(y);
}

#define MMA_TF32(c, a, b)                                                      \
    asm volatile("mma.sync.aligned.m16n8k8.row.col.f32.tf32.tf32.f32 "        \
        "{%0,%1,%2,%3}, {%4,%5,%6,%7}, {%8,%9}, {%0,%1,%2,%3};"               \
        : "+f"((c)[0]), "+f"((c)[1]), "+f"((c)[2]), "+f"((c)[3])              \
        : "r"(__float_as_uint((a)[0])), "r"(__float_as_uint((a)[1])),         \
          "r"(__float_as_uint((a)[2])), "r"(__float_as_uint((a)[3])),         \
          "r"(__float_as_uint((b)[0])), "r"(__float_as_uint((b)[1])))

// ---------------------------------------------------------------------------
// tf32 mma.sync GEMM (NT): C[M,N] = alpha * A[M,K] @ B[N,K]^T
// BM=BN=128, BK=32, 256 threads (8 warps, each 32x64), 4-stage cp.async.
// SPLIT: 3-pass split-tf32 (near-fp32 accuracy). ROUND: rna-round C on store.
// All dims divisible by tile sizes. blockIdx.z = batch.
// ---------------------------------------------------------------------------
template <bool SPLIT, bool ROUND>
__global__ __launch_bounds__(256)
void gemm_mma(const float* __restrict__ A, const float* __restrict__ B,
              float* __restrict__ C, int K, int lda, int ldb, int ldc,
              long long sA, long long sB, long long sC, float alpha)
{
    constexpr int BM = 128, BN = 128, BK = 32, S = 4;
    constexpr int LDS_ = 36;                 // padded row stride (floats)
    constexpr int ATILE = BM * LDS_;         // 4608 floats
    constexpr int STAGE = 2 * ATILE;         // A tile + B tile
    extern __shared__ float sm[];

    const int tid  = threadIdx.x;
    const int wid  = tid >> 5, lane = tid & 31;
    const int g    = lane >> 2, t = lane & 3;
    const int wm   = wid >> 1, wn = wid & 1;

    const long long rowBase = (long long)blockIdx.y * BM;
    const long long colBase = (long long)blockIdx.x * BN;
    A += (long long)blockIdx.z * sA + rowBase * lda;
    B += (long long)blockIdx.z * sB + colBase * ldb;
    C += (long long)blockIdx.z * sC;

    const int r0 = tid >> 3, c0 = tid & 7;   // 16B-chunk loader coords

    auto load_tile = [&](int kt) {
        float* as = sm + (kt & (S - 1)) * STAGE;
        float* bs = as + ATILE;
        const float* ag = A + (long long)kt * BK + c0 * 4;
        const float* bg = B + (long long)kt * BK + c0 * 4;
        #pragma unroll
        for (int i = 0; i < 4; i++) {
            int r = r0 + 32 * i;
            uint32_t d = (uint32_t)__cvta_generic_to_shared(as + r * LDS_ + c0 * 4);
            asm volatile("cp.async.cg.shared.global [%0], [%1], 16;"
                         :: "r"(d), "l"(ag + (long long)r * lda));
        }
        #pragma unroll
        for (int i = 0; i < 4; i++) {
            int r = r0 + 32 * i;
            uint32_t d = (uint32_t)__cvta_generic_to_shared(bs + r * LDS_ + c0 * 4);
            asm volatile("cp.async.cg.shared.global [%0], [%1], 16;"
                         :: "r"(d), "l"(bg + (long long)r * ldb));
        }
        asm volatile("cp.async.commit_group;");
    };

    const int NT = K / BK;
    for (int kt = 0; kt < S - 1; kt++) load_tile(kt);

    float acc[2][8][4];
    #pragma unroll
    for (int mt = 0; mt < 2; mt++)
        #pragma unroll
        for (int nt = 0; nt < 8; nt++)
            #pragma unroll
            for (int j = 0; j < 4; j++) acc[mt][nt][j] = 0.f;

    for (int kt = 0; kt < NT; kt++) {
        if (kt + S - 1 < NT) load_tile(kt + S - 1);
        const int rem = NT - kt;
        if (rem >= S)      asm volatile("cp.async.wait_group %0;" :: "n"(S - 1));
        else if (rem == 3) asm volatile("cp.async.wait_group 2;");
        else if (rem == 2) asm volatile("cp.async.wait_group 1;");
        else               asm volatile("cp.async.wait_group 0;");
        __syncthreads();

        const float* as = sm + (kt & (S - 1)) * STAGE;
        const float* bs = as + ATILE;
        const float* aw = as + (32 * wm + g) * LDS_;
        const float* bw = bs + (64 * wn + g) * LDS_;

        #pragma unroll
        for (int ks = 0; ks < 4; ks++) {
            const int k0 = ks * 8;
            float a[2][4], b[8][2];
            #pragma unroll
            for (int mt = 0; mt < 2; mt++) {
                a[mt][0] = aw[(16 * mt    ) * LDS_ + k0 + t];
                a[mt][1] = aw[(16 * mt + 8) * LDS_ + k0 + t];
                a[mt][2] = aw[(16 * mt    ) * LDS_ + k0 + t + 4];
                a[mt][3] = aw[(16 * mt + 8) * LDS_ + k0 + t + 4];
            }
            #pragma unroll
            for (int nt = 0; nt < 8; nt++) {
                b[nt][0] = bw[(8 * nt) * LDS_ + k0 + t];
                b[nt][1] = bw[(8 * nt) * LDS_ + k0 + t + 4];
            }

            if (SPLIT) {
                float al[2][4], bl[8][2];
                #pragma unroll
                for (int mt = 0; mt < 2; mt++)
                    #pragma unroll
                    for (int j = 0; j < 4; j++) {
                        float hi = rna_tf32(a[mt][j]);
                        al[mt][j] = rna_tf32(a[mt][j] - hi);
                        a[mt][j] = hi;
                    }
                #pragma unroll
                for (int nt = 0; nt < 8; nt++)
                    #pragma unroll
                    for (int j = 0; j < 2; j++) {
                        float hi = rna_tf32(b[nt][j]);
                        bl[nt][j] = rna_tf32(b[nt][j] - hi);
                        b[nt][j] = hi;
                    }
                #pragma unroll
                for (int mt = 0; mt < 2; mt++)
                    #pragma unroll
                    for (int nt = 0; nt < 8; nt++) {
                        MMA_TF32(acc[mt][nt], al[mt], b[nt]);   // lo*hi
                        MMA_TF32(acc[mt][nt], a[mt], bl[nt]);   // hi*lo
                        MMA_TF32(acc[mt][nt], a[mt], b[nt]);    // hi*hi
                    }
            } else {
                // inputs pre-rounded to tf32; HW truncation is exact
                #pragma unroll
                for (int mt = 0; mt < 2; mt++)
                    #pragma unroll
                    for (int nt = 0; nt < 8; nt++)
                        MMA_TF32(acc[mt][nt], a[mt], b[nt]);
            }
        }
        __syncthreads();
    }

    // epilogue: c0..c3 at (g, 2t), (g, 2t+1), (g+8, 2t), (g+8, 2t+1)
    #pragma unroll
    for (int mt = 0; mt < 2; mt++) {
        const long long rlo = rowBase + 32 * wm + 16 * mt + g;
        #pragma unroll
        for (int nt = 0; nt < 8; nt++) {
            const long long col = colBase + 64 * wn + 8 * nt + 2 * t;
            float2 v0, v1;
            v0.x = acc[mt][nt][0] * alpha;  v0.y = acc[mt][nt][1] * alpha;
            v1.x = acc[mt][nt][2] * alpha;  v1.y = acc[mt][nt][3] * alpha;
            if (ROUND) {
                v0.x = rna_tf32(v0.x); v0.y = rna_tf32(v0.y);
                v1.x = rna_tf32(v1.x); v1.y = rna_tf32(v1.y);
            }
            *(float2*)&C[rlo * ldc + col]       = v0;
            *(float2*)&C[(rlo + 8) * ldc + col] = v1;
        }
    }
}

// ---------------------------------------------------------------------------
// fp32 transpose: out[C,R] = in[R,C]^T
// ---------------------------------------------------------------------------
__global__ __launch_bounds__(256)
void transpose_kernel(const float* __restrict__ in, float* __restrict__ out,
                      int R, int C)
{
    __shared__ float tbuf[32][33];
    const int tx = threadIdx.x, ty = threadIdx.y;
    const int x = blockIdx.x * 32 + tx;
    const int yb = blockIdx.y * 32;
    #pragma unroll
    for (int i = 0; i < 32; i += 8)
        tbuf[ty + i][tx] = in[(long long)(yb + ty + i) * C + x];
    __syncthreads();
    const int xo = yb + tx;
    const int yo = blockIdx.x * 32 + ty;
    #pragma unroll
    for (int i = 0; i < 32; i += 8)
        out[(long long)(yo + i) * R + xo] = tbuf[tx][ty + i];
}

// ---------------------------------------------------------------------------
// row softmax (in place), tf32-rounded store (pre-rounds P for the PV GEMM)
// ---------------------------------------------------------------------------
__global__ __launch_bounds__(256)
void softmax_rows_kernel(float* __restrict__ S)
{
    float* p = S + (long long)blockIdx.x * N_;
    const int tid = threadIdx.x;

    float4 v[4];
    float mx = -1e30f;
    #pragma unroll
    for (int i = 0; i < 4; i++) {
        v[i] = *(const float4*)&p[(tid + i * 256) * 4];
        mx = fmaxf(mx, fmaxf(fmaxf(v[i].x, v[i].y), fmaxf(v[i].z, v[i].w)));
    }
    __shared__ float redmax[8];
    __shared__ float redsum[8];
    #pragma unroll
    for (int o = 16; o > 0; o >>= 1)
        mx = fmaxf(mx, __shfl_xor_sync(0xFFFFFFFFu, mx, o));
    if ((tid & 31) == 0) redmax[tid >> 5] = mx;
    __syncthreads();
    mx = redmax[0];
    #pragma unroll
    for (int i = 1; i < 8; i++) mx = fmaxf(mx, redmax[i]);

    float sum = 0.f;
    #pragma unroll
    for (int i = 0; i < 4; i++) {
        v[i].x = __expf(v[i].x - mx); v[i].y = __expf(v[i].y - mx);
        v[i].z = __expf(v[i].z - mx); v[i].w = __expf(v[i].w - mx);
        sum += v[i].x + v[i].y + v[i].z + v[i].w;
    }
    #pragma unroll
    for (int o = 16; o > 0; o >>= 1)
        sum += __shfl_xor_sync(0xFFFFFFFFu, sum, o);
    if ((tid & 31) == 0) redsum[tid >> 5] = sum;
    __syncthreads();
    sum = 0.f;
    #pragma unroll
    for (int i = 0; i < 8; i++) sum += redsum[i];

    const float inv = 1.f / sum;
    #pragma unroll
    for (int i = 0; i < 4; i++) {
        v[i].x = rna_tf32(v[i].x * inv); v[i].y = rna_tf32(v[i].y * inv);
        v[i].z = rna_tf32(v[i].z * inv); v[i].w = rna_tf32(v[i].w * inv);
        *(float4*)&p[(tid + i * 256) * 4] = v[i];
    }
}

// ---------------------------------------------------------------------------
// launch
// ---------------------------------------------------------------------------
extern "C" void kernel_launch(void* const* d_in, const int* in_sizes, int n_in,
                              void* d_out, int out_size)
{
    const float* X  = (const float*)d_in[0];
    const float* WQ = (const float*)d_in[1];
    const float* WK = (const float*)d_in[2];
    const float* WV = (const float*)d_in[3];
    float* out = (float*)d_out;

    float *Q, *K, *VT, *Sc, *WT;
    cudaGetSymbolAddress((void**)&Q,  g_Q);
    cudaGetSymbolAddress((void**)&K,  g_K);
    cudaGetSymbolAddress((void**)&VT, g_VT);
    cudaGetSymbolAddress((void**)&Sc, g_S);
    cudaGetSymbolAddress((void**)&WT, g_WT);
    float* WQT = WT;
    float* WKT = WT + (size_t)D_ * U_;
    float* WVT = WT + 2 * (size_t)D_ * U_;

    const int SMEM = 4 * 2 * 128 * 36 * 4;        // 147456 B
    cudaFuncSetAttribute(gemm_mma<true,  false>, cudaFuncAttributeMaxDynamicSharedMemorySize, SMEM);
    cudaFuncSetAttribute(gemm_mma<true,  true >, cudaFuncAttributeMaxDynamicSharedMemorySize, SMEM);
    cudaFuncSetAttribute(gemm_mma<false, false>, cudaFuncAttributeMaxDynamicSharedMemorySize, SMEM);

    const int M = B_ * N_;                        // 16384
    const long long strQ = (long long)N_ * U_;    // 4194304
    const long long strS = (long long)N_ * N_;    // 16777216

    // 1) transpose weights (fp32)
    dim3 tb(32, 8), tg(U_ / 32, D_ / 32);
    transpose_kernel<<<tg, tb>>>(WQ, WQT, D_, U_);
    transpose_kernel<<<tg, tb>>>(WK, WKT, D_, U_);
    transpose_kernel<<<tg, tb>>>(WV, WVT, D_, U_);

    // 2) projections (split tf32, near-fp32):
    //    Q = X @ WQT^T, K = X @ WKT^T       [16384,1024]
    dim3 gP(U_ / 128, M / 128, 1);
    gemm_mma<true, false><<<gP, 256, SMEM>>>(X, WQT, Q, D_, D_, D_, U_, 0, 0, 0, 1.0f);
    gemm_mma<true, false><<<gP, 256, SMEM>>>(X, WKT, K, D_, D_, D_, U_, 0, 0, 0, 1.0f);
    //    VT = WVT @ X^T  -> [1024, 16384], rna-rounded for the PV GEMM
    dim3 gV(M / 128, U_ / 128, 1);
    gemm_mma<true, true><<<gV, 256, SMEM>>>(WVT, X, VT, D_, D_, D_, M, 0, 0, 0, 1.0f);

    // 3) scores (split tf32, batched): S_b = (1/32) Q_b @ K_b^T  [4096,4096]
    dim3 gS(N_ / 128, N_ / 128, B_);
    gemm_mma<true, false><<<gS, 256, SMEM>>>(Q, K, Sc, U_, U_, U_, N_,
                                             strQ, strQ, strS, 1.0f / 32.0f);

    // 4) softmax rows in place (stores tf32-rounded probs)
    softmax_rows_kernel<<<B_ * N_, 256>>>(Sc);

    // 5) out_b = P_b @ V_b  (single-pass tf32; P, VT pre-rounded)
    dim3 gO(U_ / 128, N_ / 128, B_);
    gemm_mma<false, false><<<gO, 256, SMEM>>>(Sc, VT, out, N_, N_, M, U_,
                                              strS, (long long)N_, strQ, 1.0f);
}

// round 5
// speedup vs baseline: 3.4215x; 2.1395x over previous
#include <cuda_runtime.h>
#include <cstdint>

// Problem constants
#define B_  4
#define N_  4096
#define D_  1024
#define U_  1024

// Scratch (device globals; no runtime allocation)
__device__ float g_X [(size_t)B_ * N_ * D_];      // rna-rounded X
__device__ float g_Q [(size_t)B_ * N_ * U_];
__device__ float g_K [(size_t)B_ * N_ * U_];
__device__ float g_VT[(size_t)U_ * B_ * N_];      // V transposed: [U, B*N]
__device__ float g_S [(size_t)B_ * N_ * N_];
__device__ float g_WT[3 * (size_t)D_ * U_];       // WQ^T, WK^T, WV^T (rounded)

// ---------------------------------------------------------------------------
__device__ __forceinline__ float rna_tf32(float x) {
    uint32_t y;
    asm("cvt.rna.tf32.f32 %0, %1;" : "=r"(y) : "f"(x));
    return __uint_as_float(y);
}

#define MMA_TF32(c, a, b)                                                      \
    asm volatile("mma.sync.aligned.m16n8k8.row.col.f32.tf32.tf32.f32 "        \
        "{%0,%1,%2,%3}, {%4,%5,%6,%7}, {%8,%9}, {%0,%1,%2,%3};"               \
        : "+f"((c)[0]), "+f"((c)[1]), "+f"((c)[2]), "+f"((c)[3])              \
        : "r"(__float_as_uint((a)[0])), "r"(__float_as_uint((a)[1])),         \
          "r"(__float_as_uint((a)[2])), "r"(__float_as_uint((a)[3])),         \
          "r"(__float_as_uint((b)[0])), "r"(__float_as_uint((b)[1])))

// ---------------------------------------------------------------------------
// tf32 mma.sync GEMM (NT): C[M,N] = alpha * A[M,K] @ B[N,K]^T
// Inputs must be pre-rounded to tf32 (rna). Single-pass mma.
// BM=BN=128, BK=32, 256 threads (8 warps, each 32x64), 3-stage cp.async,
// 2 CTAs/SM. ROUND: rna-round C on store (pre-rounds next GEMM's input).
// ---------------------------------------------------------------------------
template <bool ROUND>
__global__ __launch_bounds__(256, 2)
void gemm_mma(const float* __restrict__ A, const float* __restrict__ B,
              float* __restrict__ C, int K, int lda, int ldb, int ldc,
              long long sA, long long sB, long long sC, float alpha)
{
    constexpr int BM = 128, BN = 128, BK = 32, S = 3;
    constexpr int LDS_ = 36;                 // padded row stride (floats)
    constexpr int ATILE = BM * LDS_;         // 4608 floats
    constexpr int STAGE = 2 * ATILE;         // A tile + B tile
    extern __shared__ float sm[];

    const int tid  = threadIdx.x;
    const int wid  = tid >> 5, lane = tid & 31;
    const int g    = lane >> 2, t = lane & 3;
    const int wm   = wid >> 1, wn = wid & 1;

    const long long rowBase = (long long)blockIdx.y * BM;
    const long long colBase = (long long)blockIdx.x * BN;
    A += (long long)blockIdx.z * sA + rowBase * lda;
    B += (long long)blockIdx.z * sB + colBase * ldb;
    C += (long long)blockIdx.z * sC;

    const int r0 = tid >> 3, c0 = tid & 7;   // 16B-chunk loader coords

    auto load_tile = [&](int kt) {
        float* as = sm + (kt % S) * STAGE;
        float* bs = as + ATILE;
        const float* ag = A + (long long)kt * BK + c0 * 4;
        const float* bg = B + (long long)kt * BK + c0 * 4;
        #pragma unroll
        for (int i = 0; i < 4; i++) {
            int r = r0 + 32 * i;
            uint32_t d = (uint32_t)__cvta_generic_to_shared(as + r * LDS_ + c0 * 4);
            asm volatile("cp.async.cg.shared.global [%0], [%1], 16;"
                         :: "r"(d), "l"(ag + (long long)r * lda));
        }
        #pragma unroll
        for (int i = 0; i < 4; i++) {
            int r = r0 + 32 * i;
            uint32_t d = (uint32_t)__cvta_generic_to_shared(bs + r * LDS_ + c0 * 4);
            asm volatile("cp.async.cg.shared.global [%0], [%1], 16;"
                         :: "r"(d), "l"(bg + (long long)r * ldb));
        }
        asm volatile("cp.async.commit_group;");
    };

    const int NT = K / BK;
    for (int kt = 0; kt < S - 1; kt++) load_tile(kt);

    float acc[2][8][4];
    #pragma unroll
    for (int mt = 0; mt < 2; mt++)
        #pragma unroll
        for (int nt = 0; nt < 8; nt++)
            #pragma unroll
            for (int j = 0; j < 4; j++) acc[mt][nt][j] = 0.f;

    for (int kt = 0; kt < NT; kt++) {
        if (kt + S - 1 < NT) load_tile(kt + S - 1);
        const int rem = NT - kt;
        if (rem >= S)      asm volatile("cp.async.wait_group %0;" :: "n"(S - 1));
        else if (rem == 2) asm volatile("cp.async.wait_group 1;");
        else               asm volatile("cp.async.wait_group 0;");
        __syncthreads();

        const float* as = sm + (kt % S) * STAGE;
        const float* bs = as + ATILE;
        const float* aw = as + (32 * wm + g) * LDS_;
        const float* bw = bs + (64 * wn + g) * LDS_;

        #pragma unroll
        for (int ks = 0; ks < 4; ks++) {
            const int k0 = ks * 8;
            float a[2][4], b[8][2];
            #pragma unroll
            for (int mt = 0; mt < 2; mt++) {
                a[mt][0] = aw[(16 * mt    ) * LDS_ + k0 + t];
                a[mt][1] = aw[(16 * mt + 8) * LDS_ + k0 + t];
                a[mt][2] = aw[(16 * mt    ) * LDS_ + k0 + t + 4];
                a[mt][3] = aw[(16 * mt + 8) * LDS_ + k0 + t + 4];
            }
            #pragma unroll
            for (int nt = 0; nt < 8; nt++) {
                b[nt][0] = bw[(8 * nt) * LDS_ + k0 + t];
                b[nt][1] = bw[(8 * nt) * LDS_ + k0 + t + 4];
            }
            #pragma unroll
            for (int mt = 0; mt < 2; mt++)
                #pragma unroll
                for (int nt = 0; nt < 8; nt++)
                    MMA_TF32(acc[mt][nt], a[mt], b[nt]);
        }
        __syncthreads();
    }

    // epilogue: c0..c3 at (g, 2t), (g, 2t+1), (g+8, 2t), (g+8, 2t+1)
    #pragma unroll
    for (int mt = 0; mt < 2; mt++) {
        const long long rlo = rowBase + 32 * wm + 16 * mt + g;
        #pragma unroll
        for (int nt = 0; nt < 8; nt++) {
            const long long col = colBase + 64 * wn + 8 * nt + 2 * t;
            float2 v0, v1;
            v0.x = acc[mt][nt][0] * alpha;  v0.y = acc[mt][nt][1] * alpha;
            v1.x = acc[mt][nt][2] * alpha;  v1.y = acc[mt][nt][3] * alpha;
            if (ROUND) {
                v0.x = rna_tf32(v0.x); v0.y = rna_tf32(v0.y);
                v1.x = rna_tf32(v1.x); v1.y = rna_tf32(v1.y);
            }
            *(float2*)&C[rlo * ldc + col]       = v0;
            *(float2*)&C[(rlo + 8) * ldc + col] = v1;
        }
    }
}

// ---------------------------------------------------------------------------
// elementwise rna-round to tf32
// ---------------------------------------------------------------------------
__global__ __launch_bounds__(256)
void round_tf32_kernel(const float4* __restrict__ in, float4* __restrict__ out, int n4)
{
    int i = blockIdx.x * blockDim.x + threadIdx.x;
    if (i < n4) {
        float4 v = in[i];
        v.x = rna_tf32(v.x); v.y = rna_tf32(v.y);
        v.z = rna_tf32(v.z); v.w = rna_tf32(v.w);
        out[i] = v;
    }
}

// ---------------------------------------------------------------------------
// transpose + rna round: out[C,R] = rna(in[R,C]^T)
// ---------------------------------------------------------------------------
__global__ __launch_bounds__(256)
void transpose_rna_kernel(const float* __restrict__ in, float* __restrict__ out,
                          int R, int C)
{
    __shared__ float tbuf[32][33];
    const int tx = threadIdx.x, ty = threadIdx.y;
    const int x = blockIdx.x * 32 + tx;
    const int yb = blockIdx.y * 32;
    #pragma unroll
    for (int i = 0; i < 32; i += 8)
        tbuf[ty + i][tx] = in[(long long)(yb + ty + i) * C + x];
    __syncthreads();
    const int xo = yb + tx;
    const int yo = blockIdx.x * 32 + ty;
    #pragma unroll
    for (int i = 0; i < 32; i += 8)
        out[(long long)(yo + i) * R + xo] = rna_tf32(tbuf[tx][ty + i]);
}

// ---------------------------------------------------------------------------
// row softmax (in place), tf32-rounded store (pre-rounds P for the PV GEMM)
// ---------------------------------------------------------------------------
__global__ __launch_bounds__(256)
void softmax_rows_kernel(float* __restrict__ S)
{
    float* p = S + (long long)blockIdx.x * N_;
    const int tid = threadIdx.x;

    float4 v[4];
    float mx = -1e30f;
    #pragma unroll
    for (int i = 0; i < 4; i++) {
        v[i] = *(const float4*)&p[(tid + i * 256) * 4];
        mx = fmaxf(mx, fmaxf(fmaxf(v[i].x, v[i].y), fmaxf(v[i].z, v[i].w)));
    }
    __shared__ float redmax[8];
    __shared__ float redsum[8];
    #pragma unroll
    for (int o = 16; o > 0; o >>= 1)
        mx = fmaxf(mx, __shfl_xor_sync(0xFFFFFFFFu, mx, o));
    if ((tid & 31) == 0) redmax[tid >> 5] = mx;
    __syncthreads();
    mx = redmax[0];
    #pragma unroll
    for (int i = 1; i < 8; i++) mx = fmaxf(mx, redmax[i]);

    float sum = 0.f;
    #pragma unroll
    for (int i = 0; i < 4; i++) {
        v[i].x = __expf(v[i].x - mx); v[i].y = __expf(v[i].y - mx);
        v[i].z = __expf(v[i].z - mx); v[i].w = __expf(v[i].w - mx);
        sum += v[i].x + v[i].y + v[i].z + v[i].w;
    }
    #pragma unroll
    for (int o = 16; o > 0; o >>= 1)
        sum += __shfl_xor_sync(0xFFFFFFFFu, sum, o);
    if ((tid & 31) == 0) redsum[tid >> 5] = sum;
    __syncthreads();
    sum = 0.f;
    #pragma unroll
    for (int i = 0; i < 8; i++) sum += redsum[i];

    const float inv = 1.f / sum;
    #pragma unroll
    for (int i = 0; i < 4; i++) {
        v[i].x = rna_tf32(v[i].x * inv); v[i].y = rna_tf32(v[i].y * inv);
        v[i].z = rna_tf32(v[i].z * inv); v[i].w = rna_tf32(v[i].w * inv);
        *(float4*)&p[(tid + i * 256) * 4] = v[i];
    }
}

// ---------------------------------------------------------------------------
// launch
// ---------------------------------------------------------------------------
extern "C" void kernel_launch(void* const* d_in, const int* in_sizes, int n_in,
                              void* d_out, int out_size)
{
    const float* X  = (const float*)d_in[0];
    const float* WQ = (const float*)d_in[1];
    const float* WK = (const float*)d_in[2];
    const float* WV = (const float*)d_in[3];
    float* out = (float*)d_out;

    float *Xr, *Q, *K, *VT, *Sc, *WT;
    cudaGetSymbolAddress((void**)&Xr, g_X);
    cudaGetSymbolAddress((void**)&Q,  g_Q);
    cudaGetSymbolAddress((void**)&K,  g_K);
    cudaGetSymbolAddress((void**)&VT, g_VT);
    cudaGetSymbolAddress((void**)&Sc, g_S);
    cudaGetSymbolAddress((void**)&WT, g_WT);
    float* WQT = WT;
    float* WKT = WT + (size_t)D_ * U_;
    float* WVT = WT + 2 * (size_t)D_ * U_;

    const int SMEM = 3 * 2 * 128 * 36 * 4;        // 110592 B -> 2 CTAs/SM
    cudaFuncSetAttribute(gemm_mma<false>, cudaFuncAttributeMaxDynamicSharedMemorySize, SMEM);
    cudaFuncSetAttribute(gemm_mma<true >, cudaFuncAttributeMaxDynamicSharedMemorySize, SMEM);

    const int M = B_ * N_;                        // 16384
    const long long strQ = (long long)N_ * U_;    // 4194304
    const long long strS = (long long)N_ * N_;    // 16777216

    // 1) pre-round X; transpose + round weights
    round_tf32_kernel<<<(M * D_ / 4 + 255) / 256, 256>>>((const float4*)X, (float4*)Xr, M * D_ / 4);
    dim3 tb(32, 8), tg(U_ / 32, D_ / 32);
    transpose_rna_kernel<<<tg, tb>>>(WQ, WQT, D_, U_);
    transpose_rna_kernel<<<tg, tb>>>(WK, WKT, D_, U_);
    transpose_rna_kernel<<<tg, tb>>>(WV, WVT, D_, U_);

    // 2) projections (single-pass tf32, epilogue pre-rounds for next GEMM):
    //    Q = Xr @ WQT^T, K = Xr @ WKT^T     [16384,1024]
    dim3 gP(U_ / 128, M / 128, 1);
    gemm_mma<true><<<gP, 256, SMEM>>>(Xr, WQT, Q, D_, D_, D_, U_, 0, 0, 0, 1.0f);
    gemm_mma<true><<<gP, 256, SMEM>>>(Xr, WKT, K, D_, D_, D_, U_, 0, 0, 0, 1.0f);
    //    VT = WVT @ Xr^T -> [1024, 16384], rounded
    dim3 gV(M / 128, U_ / 128, 1);
    gemm_mma<true><<<gV, 256, SMEM>>>(WVT, Xr, VT, D_, D_, D_, M, 0, 0, 0, 1.0f);

    // 3) scores (single-pass, batched): S_b = (1/32) Q_b @ K_b^T  [4096,4096]
    dim3 gS(N_ / 128, N_ / 128, B_);
    gemm_mma<false><<<gS, 256, SMEM>>>(Q, K, Sc, U_, U_, U_, N_,
                                       strQ, strQ, strS, 1.0f / 32.0f);

    // 4) softmax rows in place (stores tf32-rounded probs)
    softmax_rows_kernel<<<B_ * N_, 256>>>(Sc);

    // 5) out_b = P_b @ V_b  (single-pass; P, VT pre-rounded)
    dim3 gO(U_ / 128, N_ / 128, B_);
    gemm_mma<false><<<gO, 256, SMEM>>>(Sc, VT, out, N_, N_, M, U_,
                                       strS, (long long)N_, strQ, 1.0f);
}

// round 6
// speedup vs baseline: 4.0477x; 1.1830x over previous
#include <cuda_runtime.h>
#include <cuda_fp16.h>
#include <cstdint>

// Problem constants
#define B_  4
#define N_  4096
#define D_  1024
#define U_  1024

// Scratch (device globals; no runtime allocation)
__device__ float  g_X  [(size_t)B_ * N_ * D_];    // rna-rounded X
__device__ float  g_Q  [(size_t)B_ * N_ * U_];
__device__ float  g_K  [(size_t)B_ * N_ * U_];
__device__ __half g_VTh[(size_t)U_ * B_ * N_];    // V^T as half: [U, B*N]
__device__ float  g_S  [(size_t)B_ * N_ * N_];    // scores (fp32)
__device__ __half g_P  [(size_t)B_ * N_ * N_];    // softmax probs (half)
__device__ float  g_WT [3 * (size_t)D_ * U_];     // WQ^T, WK^T, WV^T (rounded)

// ---------------------------------------------------------------------------
__device__ __forceinline__ float rna_tf32(float x) {
    uint32_t y;
    asm("cvt.rna.tf32.f32 %0, %1;" : "=r"(y) : "f"(x));
    return __uint_as_float(y);
}

#define MMA_TF32(c, a, b)                                                      \
    asm volatile("mma.sync.aligned.m16n8k8.row.col.f32.tf32.tf32.f32 "        \
        "{%0,%1,%2,%3}, {%4,%5,%6,%7}, {%8,%9}, {%0,%1,%2,%3};"               \
        : "+f"((c)[0]), "+f"((c)[1]), "+f"((c)[2]), "+f"((c)[3])              \
        : "r"(__float_as_uint((a)[0])), "r"(__float_as_uint((a)[1])),         \
          "r"(__float_as_uint((a)[2])), "r"(__float_as_uint((a)[3])),         \
          "r"(__float_as_uint((b)[0])), "r"(__float_as_uint((b)[1])))

#define MMA_F16(c, a, b)                                                       \
    asm volatile("mma.sync.aligned.m16n8k16.row.col.f32.f16.f16.f32 "         \
        "{%0,%1,%2,%3}, {%4,%5,%6,%7}, {%8,%9}, {%0,%1,%2,%3};"               \
        : "+f"((c)[0]), "+f"((c)[1]), "+f"((c)[2]), "+f"((c)[3])              \
        : "r"((a)[0]), "r"((a)[1]), "r"((a)[2]), "r"((a)[3]),                 \
          "r"((b)[0]), "r"((b)[1]))

// ---------------------------------------------------------------------------
// tf32 mma.sync GEMM (NT): C[M,N] = alpha * A[M,K] @ B[N,K]^T
// Inputs pre-rounded to tf32. BM=BN=128, BK=32, 256 thr, 3-stage cp.async,
// 2 CTAs/SM, single barrier per k-tile.
// ROUND: rna-round C (fp32).  HOUT: store C as half (for V^T).
// ---------------------------------------------------------------------------
template <bool ROUND, bool HOUT>
__global__ __launch_bounds__(256, 2)
void gemm_tf32(const float* __restrict__ A, const float* __restrict__ B,
               void* __restrict__ Cv, int K, int lda, int ldb, int ldc,
               long long sA, long long sB, long long sC, float alpha)
{
    constexpr int BM = 128, BN = 128, BK = 32, S = 3;
    constexpr int LDS_ = 36;
    constexpr int ATILE = BM * LDS_;
    constexpr int STAGE = 2 * ATILE;
    extern __shared__ float sm[];

    const int tid  = threadIdx.x;
    const int wid  = tid >> 5, lane = tid & 31;
    const int g    = lane >> 2, t = lane & 3;
    const int wm   = wid >> 1, wn = wid & 1;

    const long long rowBase = (long long)blockIdx.y * BM;
    const long long colBase = (long long)blockIdx.x * BN;
    A += (long long)blockIdx.z * sA + rowBase * lda;
    B += (long long)blockIdx.z * sB + colBase * ldb;

    const int r0 = tid >> 3, c0 = tid & 7;

    auto load_tile = [&](int kt) {
        float* as = sm + (kt % S) * STAGE;
        float* bs = as + ATILE;
        const float* ag = A + (long long)kt * BK + c0 * 4;
        const float* bg = B + (long long)kt * BK + c0 * 4;
        #pragma unroll
        for (int i = 0; i < 4; i++) {
            int r = r0 + 32 * i;
            uint32_t d = (uint32_t)__cvta_generic_to_shared(as + r * LDS_ + c0 * 4);
            asm volatile("cp.async.cg.shared.global [%0], [%1], 16;"
                         :: "r"(d), "l"(ag + (long long)r * lda));
        }
        #pragma unroll
        for (int i = 0; i < 4; i++) {
            int r = r0 + 32 * i;
            uint32_t d = (uint32_t)__cvta_generic_to_shared(bs + r * LDS_ + c0 * 4);
            asm volatile("cp.async.cg.shared.global [%0], [%1], 16;"
                         :: "r"(d), "l"(bg + (long long)r * ldb));
        }
        asm volatile("cp.async.commit_group;");
    };

    const int NT = K / BK;
    load_tile(0);
    load_tile(1);

    float acc[2][8][4];
    #pragma unroll
    for (int mt = 0; mt < 2; mt++)
        #pragma unroll
        for (int nt = 0; nt < 8; nt++)
            #pragma unroll
            for (int j = 0; j < 4; j++) acc[mt][nt][j] = 0.f;

    for (int kt = 0; kt < NT; kt++) {
        if (kt < NT - 1) asm volatile("cp.async.wait_group 1;");
        else             asm volatile("cp.async.wait_group 0;");
        __syncthreads();
        if (kt + S - 1 < NT) load_tile(kt + S - 1);

        const float* as = sm + (kt % S) * STAGE;
        const float* bs = as + ATILE;
        const float* aw = as + (32 * wm + g) * LDS_;
        const float* bw = bs + (64 * wn + g) * LDS_;

        #pragma unroll
        for (int ks = 0; ks < 4; ks++) {
            const int k0 = ks * 8;
            float a[2][4], b[8][2];
            #pragma unroll
            for (int mt = 0; mt < 2; mt++) {
                a[mt][0] = aw[(16 * mt    ) * LDS_ + k0 + t];
                a[mt][1] = aw[(16 * mt + 8) * LDS_ + k0 + t];
                a[mt][2] = aw[(16 * mt    ) * LDS_ + k0 + t + 4];
                a[mt][3] = aw[(16 * mt + 8) * LDS_ + k0 + t + 4];
            }
            #pragma unroll
            for (int nt = 0; nt < 8; nt++) {
                b[nt][0] = bw[(8 * nt) * LDS_ + k0 + t];
                b[nt][1] = bw[(8 * nt) * LDS_ + k0 + t + 4];
            }
            #pragma unroll
            for (int mt = 0; mt < 2; mt++)
                #pragma unroll
                for (int nt = 0; nt < 8; nt++)
                    MMA_TF32(acc[mt][nt], a[mt], b[nt]);
        }
        __syncthreads();   // protect stage before next iter's load overwrite
    }

    #pragma unroll
    for (int mt = 0; mt < 2; mt++) {
        const long long rlo = rowBase + 32 * wm + 16 * mt + g;
        #pragma unroll
        for (int nt = 0; nt < 8; nt++) {
            const long long col = colBase + 64 * wn + 8 * nt + 2 * t;
            float2 v0, v1;
            v0.x = acc[mt][nt][0] * alpha;  v0.y = acc[mt][nt][1] * alpha;
            v1.x = acc[mt][nt][2] * alpha;  v1.y = acc[mt][nt][3] * alpha;
            if (HOUT) {
                __half* C = (__half*)Cv + (long long)blockIdx.z * sC;
                *(__half2*)&C[rlo * ldc + col]       = __floats2half2_rn(v0.x, v0.y);
                *(__half2*)&C[(rlo + 8) * ldc + col] = __floats2half2_rn(v1.x, v1.y);
            } else {
                float* C = (float*)Cv + (long long)blockIdx.z * sC;
                if (ROUND) {
                    v0.x = rna_tf32(v0.x); v0.y = rna_tf32(v0.y);
                    v1.x = rna_tf32(v1.x); v1.y = rna_tf32(v1.y);
                }
                *(float2*)&C[rlo * ldc + col]       = v0;
                *(float2*)&C[(rlo + 8) * ldc + col] = v1;
            }
        }
    }
}

// ---------------------------------------------------------------------------
// fp16 mma.sync GEMM (NT): C[M,N] (fp32) = A[M,K] @ B[N,K]^T, A/B half.
// BM=BN=128, BK=32 halves, m16n8k16, 3-stage cp.async, 2 CTAs/SM.
// ---------------------------------------------------------------------------
__global__ __launch_bounds__(256, 2)
void gemm_f16(const __half* __restrict__ A, const __half* __restrict__ B,
              float* __restrict__ C, int K, int lda, int ldb, int ldc,
              long long sA, long long sB, long long sC)
{
    constexpr int BM = 128, BN = 128, BK = 32, S = 3;
    constexpr int LDSH = 40;                  // halves per row (pad 8)
    constexpr int ATILE = BM * LDSH;          // 5120 halves
    constexpr int STAGE = 2 * ATILE;
    extern __shared__ __half smh[];

    const int tid  = threadIdx.x;
    const int wid  = tid >> 5, lane = tid & 31;
    const int g    = lane >> 2, t = lane & 3;
    const int wm   = wid >> 1, wn = wid & 1;

    const long long rowBase = (long long)blockIdx.y * BM;
    const long long colBase = (long long)blockIdx.x * BN;
    A += (long long)blockIdx.z * sA + rowBase * lda;
    B += (long long)blockIdx.z * sB + colBase * ldb;
    C += (long long)blockIdx.z * sC;

    const int r0 = tid >> 2, c0 = tid & 3;    // 512 chunks of 8 halves

    auto load_tile = [&](int kt) {
        __half* as = smh + (kt % S) * STAGE;
        __half* bs = as + ATILE;
        const __half* ag = A + (long long)kt * BK + c0 * 8;
        const __half* bg = B + (long long)kt * BK + c0 * 8;
        #pragma unroll
        for (int i = 0; i < 2; i++) {
            int r = r0 + 64 * i;
            uint32_t d = (uint32_t)__cvta_generic_to_shared(as + r * LDSH + c0 * 8);
            asm volatile("cp.async.cg.shared.global [%0], [%1], 16;"
                         :: "r"(d), "l"(ag + (long long)r * lda));
        }
        #pragma unroll
        for (int i = 0; i < 2; i++) {
            int r = r0 + 64 * i;
            uint32_t d = (uint32_t)__cvta_generic_to_shared(bs + r * LDSH + c0 * 8);
            asm volatile("cp.async.cg.shared.global [%0], [%1], 16;"
                         :: "r"(d), "l"(bg + (long long)r * ldb));
        }
        asm volatile("cp.async.commit_group;");
    };

    const int NT = K / BK;
    load_tile(0);
    load_tile(1);

    float acc[2][8][4];
    #pragma unroll
    for (int mt = 0; mt < 2; mt++)
        #pragma unroll
        for (int nt = 0; nt < 8; nt++)
            #pragma unroll
            for (int j = 0; j < 4; j++) acc[mt][nt][j] = 0.f;

    for (int kt = 0; kt < NT; kt++) {
        if (kt < NT - 1) asm volatile("cp.async.wait_group 1;");
        else             asm volatile("cp.async.wait_group 0;");
        __syncthreads();
        if (kt + S - 1 < NT) load_tile(kt + S - 1);

        const uint32_t* as = (const uint32_t*)(smh + (kt % S) * STAGE);
        const uint32_t* bs = as + ATILE / 2;
        const uint32_t* aw = as + (32 * wm + g) * (LDSH / 2);
        const uint32_t* bw = bs + (64 * wn + g) * (LDSH / 2);

        #pragma unroll
        for (int ks = 0; ks < 2; ks++) {
            const int k0w = ks * 8;           // k offset in b32 words
            uint32_t a[2][4], b[8][2];
            #pragma unroll
            for (int mt = 0; mt < 2; mt++) {
                a[mt][0] = aw[(16 * mt    ) * (LDSH / 2) + k0w + t];
                a[mt][1] = aw[(16 * mt + 8) * (LDSH / 2) + k0w + t];
                a[mt][2] = aw[(16 * mt    ) * (LDSH / 2) + k0w + t + 4];
                a[mt][3] = aw[(16 * mt + 8) * (LDSH / 2) + k0w + t + 4];
            }
            #pragma unroll
            for (int nt = 0; nt < 8; nt++) {
                b[nt][0] = bw[(8 * nt) * (LDSH / 2) + k0w + t];
                b[nt][1] = bw[(8 * nt) * (LDSH / 2) + k0w + t + 4];
            }
            #pragma unroll
            for (int mt = 0; mt < 2; mt++)
                #pragma unroll
                for (int nt = 0; nt < 8; nt++)
                    MMA_F16(acc[mt][nt], a[mt], b[nt]);
        }
        __syncthreads();
    }

    #pragma unroll
    for (int mt = 0; mt < 2; mt++) {
        const long long rlo = rowBase + 32 * wm + 16 * mt + g;
        #pragma unroll
        for (int nt = 0; nt < 8; nt++) {
            const long long col = colBase + 64 * wn + 8 * nt + 2 * t;
            *(float2*)&C[rlo * ldc + col]       = make_float2(acc[mt][nt][0], acc[mt][nt][1]);
            *(float2*)&C[(rlo + 8) * ldc + col] = make_float2(acc[mt][nt][2], acc[mt][nt][3]);
        }
    }
}

// ---------------------------------------------------------------------------
__global__ __launch_bounds__(256)
void round_tf32_kernel(const float4* __restrict__ in, float4* __restrict__ out, int n4)
{
    int i = blockIdx.x * blockDim.x + threadIdx.x;
    if (i < n4) {
        float4 v = in[i];
        v.x = rna_tf32(v.x); v.y = rna_tf32(v.y);
        v.z = rna_tf32(v.z); v.w = rna_tf32(v.w);
        out[i] = v;
    }
}

__global__ __launch_bounds__(256)
void transpose_rna_kernel(const float* __restrict__ in, float* __restrict__ out,
                          int R, int C)
{
    __shared__ float tbuf[32][33];
    const int tx = threadIdx.x, ty = threadIdx.y;
    const int x = blockIdx.x * 32 + tx;
    const int yb = blockIdx.y * 32;
    #pragma unroll
    for (int i = 0; i < 32; i += 8)
        tbuf[ty + i][tx] = in[(long long)(yb + ty + i) * C + x];
    __syncthreads();
    const int xo = yb + tx;
    const int yo = blockIdx.x * 32 + ty;
    #pragma unroll
    for (int i = 0; i < 32; i += 8)
        out[(long long)(yo + i) * R + xo] = rna_tf32(tbuf[tx][ty + i]);
}

// ---------------------------------------------------------------------------
// row softmax: read fp32 scores, write half probs
// ---------------------------------------------------------------------------
__global__ __launch_bounds__(256)
void softmax_rows_kernel(const float* __restrict__ S, __half* __restrict__ P)
{
    const float* p = S + (long long)blockIdx.x * N_;
    __half* q = P + (long long)blockIdx.x * N_;
    const int tid = threadIdx.x;

    float4 v[4];
    float mx = -1e30f;
    #pragma unroll
    for (int i = 0; i < 4; i++) {
        v[i] = *(const float4*)&p[(tid + i * 256) * 4];
        mx = fmaxf(mx, fmaxf(fmaxf(v[i].x, v[i].y), fmaxf(v[i].z, v[i].w)));
    }
    __shared__ float redmax[8];
    __shared__ float redsum[8];
    #pragma unroll
    for (int o = 16; o > 0; o >>= 1)
        mx = fmaxf(mx, __shfl_xor_sync(0xFFFFFFFFu, mx, o));
    if ((tid & 31) == 0) redmax[tid >> 5] = mx;
    __syncthreads();
    mx = redmax[0];
    #pragma unroll
    for (int i = 1; i < 8; i++) mx = fmaxf(mx, redmax[i]);

    float sum = 0.f;
    #pragma unroll
    for (int i = 0; i < 4; i++) {
        v[i].x = __expf(v[i].x - mx); v[i].y = __expf(v[i].y - mx);
        v[i].z = __expf(v[i].z - mx); v[i].w = __expf(v[i].w - mx);
        sum += v[i].x + v[i].y + v[i].z + v[i].w;
    }
    #pragma unroll
    for (int o = 16; o > 0; o >>= 1)
        sum += __shfl_xor_sync(0xFFFFFFFFu, sum, o);
    if ((tid & 31) == 0) redsum[tid >> 5] = sum;
    __syncthreads();
    sum = 0.f;
    #pragma unroll
    for (int i = 0; i < 8; i++) sum += redsum[i];

    const float inv = 1.f / sum;
    #pragma unroll
    for (int i = 0; i < 4; i++) {
        __half2 h0 = __floats2half2_rn(v[i].x * inv, v[i].y * inv);
        __half2 h1 = __floats2half2_rn(v[i].z * inv, v[i].w * inv);
        *(__half2*)&q[(tid + i * 256) * 4]     = h0;
        *(__half2*)&q[(tid + i * 256) * 4 + 2] = h1;
    }
}

// ---------------------------------------------------------------------------
extern "C" void kernel_launch(void* const* d_in, const int* in_sizes, int n_in,
                              void* d_out, int out_size)
{
    const float* X  = (const float*)d_in[0];
    const float* WQ = (const float*)d_in[1];
    const float* WK = (const float*)d_in[2];
    const float* WV = (const float*)d_in[3];
    float* out = (float*)d_out;

    float *Xr, *Q, *K, *Sc, *WT;
    __half *VTh, *P;
    cudaGetSymbolAddress((void**)&Xr,  g_X);
    cudaGetSymbolAddress((void**)&Q,   g_Q);
    cudaGetSymbolAddress((void**)&K,   g_K);
    cudaGetSymbolAddress((void**)&VTh, g_VTh);
    cudaGetSymbolAddress((void**)&Sc,  g_S);
    cudaGetSymbolAddress((void**)&P,   g_P);
    cudaGetSymbolAddress((void**)&WT,  g_WT);
    float* WQT = WT;
    float* WKT = WT + (size_t)D_ * U_;
    float* WVT = WT + 2 * (size_t)D_ * U_;

    const int SMEM_T = 3 * 2 * 128 * 36 * 4;      // 110592 B
    const int SMEM_H = 3 * 2 * 128 * 40 * 2;      // 61440 B
    cudaFuncSetAttribute(gemm_tf32<true,  false>, cudaFuncAttributeMaxDynamicSharedMemorySize, SMEM_T);
    cudaFuncSetAttribute(gemm_tf32<false, false>, cudaFuncAttributeMaxDynamicSharedMemorySize, SMEM_T);
    cudaFuncSetAttribute(gemm_tf32<false, true >, cudaFuncAttributeMaxDynamicSharedMemorySize, SMEM_T);
    cudaFuncSetAttribute(gemm_f16,                cudaFuncAttributeMaxDynamicSharedMemorySize, SMEM_H);

    const int M = B_ * N_;                        // 16384
    const long long strQ = (long long)N_ * U_;
    const long long strS = (long long)N_ * N_;

    // 1) pre-round X; transpose + round weights
    round_tf32_kernel<<<(M * D_ / 4 + 255) / 256, 256>>>((const float4*)X, (float4*)Xr, M * D_ / 4);
    dim3 tb(32, 8), tg(U_ / 32, D_ / 32);
    transpose_rna_kernel<<<tg, tb>>>(WQ, WQT, D_, U_);
    transpose_rna_kernel<<<tg, tb>>>(WK, WKT, D_, U_);
    transpose_rna_kernel<<<tg, tb>>>(WV, WVT, D_, U_);

    // 2) projections: Q = Xr @ WQT^T, K = Xr @ WKT^T (tf32, rounded out)
    dim3 gP(U_ / 128, M / 128, 1);
    gemm_tf32<true, false><<<gP, 256, SMEM_T>>>(Xr, WQT, Q, D_, D_, D_, U_, 0, 0, 0, 1.0f);
    gemm_tf32<true, false><<<gP, 256, SMEM_T>>>(Xr, WKT, K, D_, D_, D_, U_, 0, 0, 0, 1.0f);
    //    VTh = WVT @ Xr^T -> [1024, 16384] half
    dim3 gV(M / 128, U_ / 128, 1);
    gemm_tf32<false, true><<<gV, 256, SMEM_T>>>(WVT, Xr, VTh, D_, D_, D_, M, 0, 0, 0, 1.0f);

    // 3) scores: S_b = (1/32) Q_b @ K_b^T  (tf32, batched)
    dim3 gS(N_ / 128, N_ / 128, B_);
    gemm_tf32<false, false><<<gS, 256, SMEM_T>>>(Q, K, Sc, U_, U_, U_, N_,
                                                 strQ, strQ, strS, 1.0f / 32.0f);

    // 4) softmax: fp32 scores -> half probs
    softmax_rows_kernel<<<B_ * N_, 256>>>(Sc, P);

    // 5) out_b = P_b @ V_b  (fp16 mma, fp32 accum/out)
    dim3 gO(U_ / 128, N_ / 128, B_);
    gemm_f16<<<gO, 256, SMEM_H>>>(P, VTh, out, N_, N_, M, U_,
                                  strS, (long long)N_, strQ);
}

// round 7
// speedup vs baseline: 5.7913x; 1.4307x over previous
#include <cuda_runtime.h>
#include <cuda_fp16.h>
#include <cstdint>

// Problem constants
#define B_  4
#define N_  4096
#define D_  1024
#define U_  1024

// Scratch (device globals; no runtime allocation)
__device__ __half g_Xh [(size_t)B_ * N_ * D_];    // X as half
__device__ __half g_Qh [(size_t)B_ * N_ * U_];    // Q as half
__device__ __half g_Kh [(size_t)B_ * N_ * U_];    // K as half
__device__ __half g_VTh[(size_t)U_ * B_ * N_];    // V^T as half: [U, B*N]
__device__ float  g_S  [(size_t)B_ * N_ * N_];    // scores (fp32)
__device__ __half g_P  [(size_t)B_ * N_ * N_];    // softmax probs (half)
__device__ __half g_WTh[3 * (size_t)D_ * U_];     // WQ^T, WK^T, WV^T (half)

// ---------------------------------------------------------------------------
#define MMA_F16(c, a, b)                                                       \
    asm volatile("mma.sync.aligned.m16n8k16.row.col.f32.f16.f16.f32 "         \
        "{%0,%1,%2,%3}, {%4,%5,%6,%7}, {%8,%9}, {%0,%1,%2,%3};"               \
        : "+f"((c)[0]), "+f"((c)[1]), "+f"((c)[2]), "+f"((c)[3])              \
        : "r"((a)[0]), "r"((a)[1]), "r"((a)[2]), "r"((a)[3]),                 \
          "r"((b)[0]), "r"((b)[1]))

// ---------------------------------------------------------------------------
// fp16 mma.sync GEMM (NT): C[M,N] = alpha * A[M,K] @ B[N,K]^T, A/B half,
// fp32 accumulate. BM=BN=128, BK=32, m16n8k16, 256 threads (8 warps, each
// 32x64), 3-stage cp.async, 2 CTAs/SM, single barrier per k-tile.
// HOUT: store C as half (rounds it as the next GEMM's input); else fp32.
// ---------------------------------------------------------------------------
template <bool HOUT>
__global__ __launch_bounds__(256, 2)
void gemm_f16(const __half* __restrict__ A, const __half* __restrict__ B,
              void* __restrict__ Cv, int K, int lda, int ldb, int ldc,
              long long sA, long long sB, long long sC, float alpha)
{
    constexpr int BM = 128, BN = 128, BK = 32, S = 3;
    constexpr int LDSH = 40;                  // halves per row (pad 8)
    constexpr int ATILE = BM * LDSH;          // 5120 halves
    constexpr int STAGE = 2 * ATILE;
    extern __shared__ __half smh[];

    const int tid  = threadIdx.x;
    const int wid  = tid >> 5, lane = tid & 31;
    const int g    = lane >> 2, t = lane & 3;
    const int wm   = wid >> 1, wn = wid & 1;

    const long long rowBase = (long long)blockIdx.y * BM;
    const long long colBase = (long long)blockIdx.x * BN;
    A += (long long)blockIdx.z * sA + rowBase * lda;
    B += (long long)blockIdx.z * sB + colBase * ldb;

    const int r0 = tid >> 2, c0 = tid & 3;    // 512 chunks of 8 halves

    auto load_tile = [&](int kt) {
        __half* as = smh + (kt % S) * STAGE;
        __half* bs = as + ATILE;
        const __half* ag = A + (long long)kt * BK + c0 * 8;
        const __half* bg = B + (long long)kt * BK + c0 * 8;
        #pragma unroll
        for (int i = 0; i < 2; i++) {
            int r = r0 + 64 * i;
            uint32_t d = (uint32_t)__cvta_generic_to_shared(as + r * LDSH + c0 * 8);
            asm volatile("cp.async.cg.shared.global [%0], [%1], 16;"
                         :: "r"(d), "l"(ag + (long long)r * lda));
        }
        #pragma unroll
        for (int i = 0; i < 2; i++) {
            int r = r0 + 64 * i;
            uint32_t d = (uint32_t)__cvta_generic_to_shared(bs + r * LDSH + c0 * 8);
            asm volatile("cp.async.cg.shared.global [%0], [%1], 16;"
                         :: "r"(d), "l"(bg + (long long)r * ldb));
        }
        asm volatile("cp.async.commit_group;");
    };

    const int NT = K / BK;
    load_tile(0);
    load_tile(1);

    float acc[2][8][4];
    #pragma unroll
    for (int mt = 0; mt < 2; mt++)
        #pragma unroll
        for (int nt = 0; nt < 8; nt++)
            #pragma unroll
            for (int j = 0; j < 4; j++) acc[mt][nt][j] = 0.f;

    for (int kt = 0; kt < NT; kt++) {
        if (kt < NT - 1) asm volatile("cp.async.wait_group 1;");
        else             asm volatile("cp.async.wait_group 0;");
        __syncthreads();
        if (kt + S - 1 < NT) load_tile(kt + S - 1);

        const uint32_t* as = (const uint32_t*)(smh + (kt % S) * STAGE);
        const uint32_t* bs = as + ATILE / 2;
        const uint32_t* aw = as + (32 * wm + g) * (LDSH / 2);
        const uint32_t* bw = bs + (64 * wn + g) * (LDSH / 2);

        #pragma unroll
        for (int ks = 0; ks < 2; ks++) {
            const int k0w = ks * 8;           // k offset in b32 words
            uint32_t a[2][4], b[8][2];
            #pragma unroll
            for (int mt = 0; mt < 2; mt++) {
                a[mt][0] = aw[(16 * mt    ) * (LDSH / 2) + k0w + t];
                a[mt][1] = aw[(16 * mt + 8) * (LDSH / 2) + k0w + t];
                a[mt][2] = aw[(16 * mt    ) * (LDSH / 2) + k0w + t + 4];
                a[mt][3] = aw[(16 * mt + 8) * (LDSH / 2) + k0w + t + 4];
            }
            #pragma unroll
            for (int nt = 0; nt < 8; nt++) {
                b[nt][0] = bw[(8 * nt) * (LDSH / 2) + k0w + t];
                b[nt][1] = bw[(8 * nt) * (LDSH / 2) + k0w + t + 4];
            }
            #pragma unroll
            for (int mt = 0; mt < 2; mt++)
                #pragma unroll
                for (int nt = 0; nt < 8; nt++)
                    MMA_F16(acc[mt][nt], a[mt], b[nt]);
        }
        __syncthreads();
    }

    #pragma unroll
    for (int mt = 0; mt < 2; mt++) {
        const long long rlo = rowBase + 32 * wm + 16 * mt + g;
        #pragma unroll
        for (int nt = 0; nt < 8; nt++) {
            const long long col = colBase + 64 * wn + 8 * nt + 2 * t;
            float2 v0, v1;
            v0.x = acc[mt][nt][0] * alpha;  v0.y = acc[mt][nt][1] * alpha;
            v1.x = acc[mt][nt][2] * alpha;  v1.y = acc[mt][nt][3] * alpha;
            if (HOUT) {
                __half* C = (__half*)Cv + (long long)blockIdx.z * sC;
                *(__half2*)&C[rlo * ldc + col]       = __floats2half2_rn(v0.x, v0.y);
                *(__half2*)&C[(rlo + 8) * ldc + col] = __floats2half2_rn(v1.x, v1.y);
            } else {
                float* C = (float*)Cv + (long long)blockIdx.z * sC;
                *(float2*)&C[rlo * ldc + col]       = v0;
                *(float2*)&C[(rlo + 8) * ldc + col] = v1;
            }
        }
    }
}

// ---------------------------------------------------------------------------
// fp32 -> half conversion (vectorized)
// ---------------------------------------------------------------------------
__global__ __launch_bounds__(256)
void to_half_kernel(const float4* __restrict__ in, __half2* __restrict__ out, int n4)
{
    int i = blockIdx.x * blockDim.x + threadIdx.x;
    if (i < n4) {
        float4 v = in[i];
        out[2 * i]     = __floats2half2_rn(v.x, v.y);
        out[2 * i + 1] = __floats2half2_rn(v.z, v.w);
    }
}

// ---------------------------------------------------------------------------
// transpose + half convert: out[C,R] = half(in[R,C]^T)
// ---------------------------------------------------------------------------
__global__ __launch_bounds__(256)
void transpose_half_kernel(const float* __restrict__ in, __half* __restrict__ out,
                           int R, int C)
{
    __shared__ float tbuf[32][33];
    const int tx = threadIdx.x, ty = threadIdx.y;
    const int x = blockIdx.x * 32 + tx;
    const int yb = blockIdx.y * 32;
    #pragma unroll
    for (int i = 0; i < 32; i += 8)
        tbuf[ty + i][tx] = in[(long long)(yb + ty + i) * C + x];
    __syncthreads();
    const int xo = yb + tx;
    const int yo = blockIdx.x * 32 + ty;
    #pragma unroll
    for (int i = 0; i < 32; i += 8)
        out[(long long)(yo + i) * R + xo] = __float2half_rn(tbuf[tx][ty + i]);
}

// ---------------------------------------------------------------------------
// row softmax: read fp32 scores, write half probs
// ---------------------------------------------------------------------------
__global__ __launch_bounds__(256)
void softmax_rows_kernel(const float* __restrict__ S, __half* __restrict__ P)
{
    const float* p = S + (long long)blockIdx.x * N_;
    __half* q = P + (long long)blockIdx.x * N_;
    const int tid = threadIdx.x;

    float4 v[4];
    float mx = -1e30f;
    #pragma unroll
    for (int i = 0; i < 4; i++) {
        v[i] = *(const float4*)&p[(tid + i * 256) * 4];
        mx = fmaxf(mx, fmaxf(fmaxf(v[i].x, v[i].y), fmaxf(v[i].z, v[i].w)));
    }
    __shared__ float redmax[8];
    __shared__ float redsum[8];
    #pragma unroll
    for (int o = 16; o > 0; o >>= 1)
        mx = fmaxf(mx, __shfl_xor_sync(0xFFFFFFFFu, mx, o));
    if ((tid & 31) == 0) redmax[tid >> 5] = mx;
    __syncthreads();
    mx = redmax[0];
    #pragma unroll
    for (int i = 1; i < 8; i++) mx = fmaxf(mx, redmax[i]);

    float sum = 0.f;
    #pragma unroll
    for (int i = 0; i < 4; i++) {
        v[i].x = __expf(v[i].x - mx); v[i].y = __expf(v[i].y - mx);
        v[i].z = __expf(v[i].z - mx); v[i].w = __expf(v[i].w - mx);
        sum += v[i].x + v[i].y + v[i].z + v[i].w;
    }
    #pragma unroll
    for (int o = 16; o > 0; o >>= 1)
        sum += __shfl_xor_sync(0xFFFFFFFFu, sum, o);
    if ((tid & 31) == 0) redsum[tid >> 5] = sum;
    __syncthreads();
    sum = 0.f;
    #pragma unroll
    for (int i = 0; i < 8; i++) sum += redsum[i];

    const float inv = 1.f / sum;
    #pragma unroll
    for (int i = 0; i < 4; i++) {
        __half2 h0 = __floats2half2_rn(v[i].x * inv, v[i].y * inv);
        __half2 h1 = __floats2half2_rn(v[i].z * inv, v[i].w * inv);
        *(__half2*)&q[(tid + i * 256) * 4]     = h0;
        *(__half2*)&q[(tid + i * 256) * 4 + 2] = h1;
    }
}

// ---------------------------------------------------------------------------
extern "C" void kernel_launch(void* const* d_in, const int* in_sizes, int n_in,
                              void* d_out, int out_size)
{
    const float* X  = (const float*)d_in[0];
    const float* WQ = (const float*)d_in[1];
    const float* WK = (const float*)d_in[2];
    const float* WV = (const float*)d_in[3];
    float* out = (float*)d_out;

    __half *Xh, *Qh, *Kh, *VTh, *P, *WTh;
    float *Sc;
    cudaGetSymbolAddress((void**)&Xh,  g_Xh);
    cudaGetSymbolAddress((void**)&Qh,  g_Qh);
    cudaGetSymbolAddress((void**)&Kh,  g_Kh);
    cudaGetSymbolAddress((void**)&VTh, g_VTh);
    cudaGetSymbolAddress((void**)&Sc,  g_S);
    cudaGetSymbolAddress((void**)&P,   g_P);
    cudaGetSymbolAddress((void**)&WTh, g_WTh);
    __half* WQTh = WTh;
    __half* WKTh = WTh + (size_t)D_ * U_;
    __half* WVTh = WTh + 2 * (size_t)D_ * U_;

    const int SMEM_H = 3 * 2 * 128 * 40 * 2;      // 61440 B
    cudaFuncSetAttribute(gemm_f16<true >, cudaFuncAttributeMaxDynamicSharedMemorySize, SMEM_H);
    cudaFuncSetAttribute(gemm_f16<false>, cudaFuncAttributeMaxDynamicSharedMemorySize, SMEM_H);

    const int M = B_ * N_;                        // 16384
    const long long strQ = (long long)N_ * U_;
    const long long strS = (long long)N_ * N_;

    // 1) X -> half; transpose weights -> half
    to_half_kernel<<<(M * D_ / 4 + 255) / 256, 256>>>((const float4*)X, (__half2*)Xh, M * D_ / 4);
    dim3 tb(32, 8), tg(U_ / 32, D_ / 32);
    transpose_half_kernel<<<tg, tb>>>(WQ, WQTh, D_, U_);
    transpose_half_kernel<<<tg, tb>>>(WK, WKTh, D_, U_);
    transpose_half_kernel<<<tg, tb>>>(WV, WVTh, D_, U_);

    // 2) projections (fp16 mma, half out):
    //    Q = Xh @ WQTh^T, K = Xh @ WKTh^T   [16384,1024]
    dim3 gP(U_ / 128, M / 128, 1);
    gemm_f16<true><<<gP, 256, SMEM_H>>>(Xh, WQTh, Qh, D_, D_, D_, U_, 0, 0, 0, 1.0f);
    gemm_f16<true><<<gP, 256, SMEM_H>>>(Xh, WKTh, Kh, D_, D_, D_, U_, 0, 0, 0, 1.0f);
    //    VTh = WVTh @ Xh^T -> [1024, 16384] half
    dim3 gV(M / 128, U_ / 128, 1);
    gemm_f16<true><<<gV, 256, SMEM_H>>>(WVTh, Xh, VTh, D_, D_, D_, M, 0, 0, 0, 1.0f);

    // 3) scores: S_b = (1/32) Qh_b @ Kh_b^T  (fp16 mma, fp32 out, batched)
    dim3 gS(N_ / 128, N_ / 128, B_);
    gemm_f16<false><<<gS, 256, SMEM_H>>>(Qh, Kh, Sc, U_, U_, U_, N_,
                                         strQ, strQ, strS, 1.0f / 32.0f);

    // 4) softmax: fp32 scores -> half probs
    softmax_rows_kernel<<<B_ * N_, 256>>>(Sc, P);

    // 5) out_b = P_b @ V_b  (fp16 mma, fp32 out)
    dim3 gO(U_ / 128, N_ / 128, B_);
    gemm_f16<false><<<gO, 256, SMEM_H>>>(P, VTh, out, N_, N_, M, U_,
                                         strS, (long long)N_, strQ, 1.0f);
}

// round 8
// speedup vs baseline: 7.1930x; 1.2420x over previous
#include <cuda_runtime.h>
#include <cuda_fp16.h>
#include <cstdint>

// Problem constants
#define B_  4
#define N_  4096
#define D_  1024
#define U_  1024

// Scratch (device globals; no runtime allocation)
__device__ __half g_Xh [(size_t)B_ * N_ * D_];    // X as half
__device__ __half g_Qh [(size_t)B_ * N_ * U_];    // Q as half
__device__ __half g_Kh [(size_t)B_ * N_ * U_];    // K as half
__device__ __half g_VTh[(size_t)U_ * B_ * N_];    // V^T as half: [U, B*N]
__device__ float  g_S  [(size_t)B_ * N_ * N_];    // scores (fp32)
__device__ __half g_P  [(size_t)B_ * N_ * N_];    // softmax probs (half)
__device__ __half g_WTh[3 * (size_t)D_ * U_];     // WQ^T, WK^T, WV^T (half)

// ---------------------------------------------------------------------------
#define MMA_F16(c, a, b)                                                       \
    asm volatile("mma.sync.aligned.m16n8k16.row.col.f32.f16.f16.f32 "         \
        "{%0,%1,%2,%3}, {%4,%5,%6,%7}, {%8,%9}, {%0,%1,%2,%3};"               \
        : "+f"((c)[0]), "+f"((c)[1]), "+f"((c)[2]), "+f"((c)[3])              \
        : "r"((a)[0]), "r"((a)[1]), "r"((a)[2]), "r"((a)[3]),                 \
          "r"((b)[0]), "r"((b)[1]))

#define LDSM_X4(r0, r1, r2, r3, addr)                                          \
    asm volatile("ldmatrix.sync.aligned.m8n8.x4.shared.b16 {%0,%1,%2,%3}, [%4];" \
        : "=r"(r0), "=r"(r1), "=r"(r2), "=r"(r3) : "r"(addr))

// ---------------------------------------------------------------------------
// fp16 mma.sync GEMM (NT): C[M,N] = alpha * A[M,K] @ B[N,K]^T, fp32 accum.
// BM=BN=128, BK=64, m16n8k16 + ldmatrix, 256 threads (8 warps, each 32x64),
// 3-stage cp.async, 2 CTAs/SM, one barrier pair per 64-deep k-tile.
// HOUT: store C as half (rounds it as the next GEMM's input); else fp32.
// ---------------------------------------------------------------------------
template <bool HOUT>
__global__ __launch_bounds__(256, 2)
void gemm_f16(const __half* __restrict__ A, const __half* __restrict__ B,
              void* __restrict__ Cv, int K, int lda, int ldb, int ldc,
              long long sA, long long sB, long long sC, float alpha)
{
    constexpr int BM = 128, BN = 128, BK = 64, S = 3;
    constexpr int LDSH = 72;                   // halves per row (64 + 8 pad)
    constexpr int ATILE = BM * LDSH;           // 9216 halves
    constexpr int STAGE = 2 * ATILE;           // 18432 halves = 36864 B
    extern __shared__ __half smh[];

    const int tid  = threadIdx.x;
    const int wid  = tid >> 5, lane = tid & 31;
    const int g    = lane >> 2, t = lane & 3;
    const int wm   = wid >> 1, wn = wid & 1;

    const long long rowBase = (long long)blockIdx.y * BM;
    const long long colBase = (long long)blockIdx.x * BN;
    A += (long long)blockIdx.z * sA + rowBase * lda;
    B += (long long)blockIdx.z * sB + colBase * ldb;

    const uint32_t smem0 = (uint32_t)__cvta_generic_to_shared(smh);

    // ldmatrix per-lane row/col offsets (halves), relative to tile base:
    //   A (x4 -> a0..a3): row = lane&15 (+16*mt), col = 8*(lane>>4) (+16*ks)
    //   B (x4 -> b[2p][0],b[2p][1],b[2p+1][0],b[2p+1][1]):
    //     row = 8*(lane>>4) + (lane&7) (+16*p), col = 8*((lane>>3)&1) (+16*ks)
    const uint32_t aoff = (uint32_t)((32 * wm + (lane & 15)) * LDSH + 8 * (lane >> 4));
    const uint32_t boff = (uint32_t)((64 * wn + ((lane >> 4) << 3) + (lane & 7)) * LDSH
                                     + 8 * ((lane >> 3) & 1));

    const int r0 = tid >> 3, c0 = tid & 7;     // loader: 16B chunk coords

    auto load_tile = [&](int kt) {
        uint32_t as = smem0 + (uint32_t)((kt % S) * STAGE) * 2;
        uint32_t bs = as + ATILE * 2;
        const __half* ag = A + (long long)kt * BK;
        const __half* bg = B + (long long)kt * BK;
        #pragma unroll
        for (int i = 0; i < 4; i++) {
            int r = r0 + 32 * i;
            uint32_t d = as + (uint32_t)(r * LDSH + c0 * 8) * 2;
            asm volatile("cp.async.cg.shared.global [%0], [%1], 16;"
                         :: "r"(d), "l"(ag + (long long)r * lda + c0 * 8));
        }
        #pragma unroll
        for (int i = 0; i < 4; i++) {
            int r = r0 + 32 * i;
            uint32_t d = bs + (uint32_t)(r * LDSH + c0 * 8) * 2;
            asm volatile("cp.async.cg.shared.global [%0], [%1], 16;"
                         :: "r"(d), "l"(bg + (long long)r * ldb + c0 * 8));
        }
        asm volatile("cp.async.commit_group;");
    };

    const int NT = K / BK;
    load_tile(0);
    load_tile(1);

    float acc[2][8][4];
    #pragma unroll
    for (int mt = 0; mt < 2; mt++)
        #pragma unroll
        for (int nt = 0; nt < 8; nt++)
            #pragma unroll
            for (int j = 0; j < 4; j++) acc[mt][nt][j] = 0.f;

    for (int kt = 0; kt < NT; kt++) {
        if (kt < NT - 1) asm volatile("cp.async.wait_group 1;");
        else             asm volatile("cp.async.wait_group 0;");
        __syncthreads();
        if (kt + S - 1 < NT) load_tile(kt + S - 1);

        const uint32_t as = smem0 + (uint32_t)((kt % S) * STAGE) * 2;
        const uint32_t bs = as + ATILE * 2;
        const uint32_t aaddr = as + aoff * 2;
        const uint32_t baddr = bs + boff * 2;

        #pragma unroll
        for (int ks = 0; ks < 4; ks++) {
            const uint32_t kb = (uint32_t)(16 * ks) * 2;   // byte offset in k
            uint32_t a[2][4], b[8][2];
            #pragma unroll
            for (int mt = 0; mt < 2; mt++)
                LDSM_X4(a[mt][0], a[mt][1], a[mt][2], a[mt][3],
                        aaddr + (uint32_t)(16 * mt * LDSH) * 2 + kb);
            #pragma unroll
            for (int p = 0; p < 4; p++)
                LDSM_X4(b[2 * p][0], b[2 * p][1], b[2 * p + 1][0], b[2 * p + 1][1],
                        baddr + (uint32_t)(16 * p * LDSH) * 2 + kb);
            #pragma unroll
            for (int mt = 0; mt < 2; mt++)
                #pragma unroll
                for (int nt = 0; nt < 8; nt++)
                    MMA_F16(acc[mt][nt], a[mt], b[nt]);
        }
        __syncthreads();
    }

    #pragma unroll
    for (int mt = 0; mt < 2; mt++) {
        const long long rlo = rowBase + 32 * wm + 16 * mt + g;
        #pragma unroll
        for (int nt = 0; nt < 8; nt++) {
            const long long col = colBase + 64 * wn + 8 * nt + 2 * t;
            float2 v0, v1;
            v0.x = acc[mt][nt][0] * alpha;  v0.y = acc[mt][nt][1] * alpha;
            v1.x = acc[mt][nt][2] * alpha;  v1.y = acc[mt][nt][3] * alpha;
            if (HOUT) {
                __half* C = (__half*)Cv + (long long)blockIdx.z * sC;
                *(__half2*)&C[rlo * ldc + col]       = __floats2half2_rn(v0.x, v0.y);
                *(__half2*)&C[(rlo + 8) * ldc + col] = __floats2half2_rn(v1.x, v1.y);
            } else {
                float* C = (float*)Cv + (long long)blockIdx.z * sC;
                *(float2*)&C[rlo * ldc + col]       = v0;
                *(float2*)&C[(rlo + 8) * ldc + col] = v1;
            }
        }
    }
}

// ---------------------------------------------------------------------------
__global__ __launch_bounds__(256)
void to_half_kernel(const float4* __restrict__ in, __half2* __restrict__ out, int n4)
{
    int i = blockIdx.x * blockDim.x + threadIdx.x;
    if (i < n4) {
        float4 v = in[i];
        out[2 * i]     = __floats2half2_rn(v.x, v.y);
        out[2 * i + 1] = __floats2half2_rn(v.z, v.w);
    }
}

__global__ __launch_bounds__(256)
void transpose_half_kernel(const float* __restrict__ in, __half* __restrict__ out,
                           int R, int C)
{
    __shared__ float tbuf[32][33];
    const int tx = threadIdx.x, ty = threadIdx.y;
    const int x = blockIdx.x * 32 + tx;
    const int yb = blockIdx.y * 32;
    #pragma unroll
    for (int i = 0; i < 32; i += 8)
        tbuf[ty + i][tx] = in[(long long)(yb + ty + i) * C + x];
    __syncthreads();
    const int xo = yb + tx;
    const int yo = blockIdx.x * 32 + ty;
    #pragma unroll
    for (int i = 0; i < 32; i += 8)
        out[(long long)(yo + i) * R + xo] = __float2half_rn(tbuf[tx][ty + i]);
}

// ---------------------------------------------------------------------------
__global__ __launch_bounds__(256)
void softmax_rows_kernel(const float* __restrict__ S, __half* __restrict__ P)
{
    const float* p = S + (long long)blockIdx.x * N_;
    __half* q = P + (long long)blockIdx.x * N_;
    const int tid = threadIdx.x;

    float4 v[4];
    float mx = -1e30f;
    #pragma unroll
    for (int i = 0; i < 4; i++) {
        v[i] = *(const float4*)&p[(tid + i * 256) * 4];
        mx = fmaxf(mx, fmaxf(fmaxf(v[i].x, v[i].y), fmaxf(v[i].z, v[i].w)));
    }
    __shared__ float redmax[8];
    __shared__ float redsum[8];
    #pragma unroll
    for (int o = 16; o > 0; o >>= 1)
        mx = fmaxf(mx, __shfl_xor_sync(0xFFFFFFFFu, mx, o));
    if ((tid & 31) == 0) redmax[tid >> 5] = mx;
    __syncthreads();
    mx = redmax[0];
    #pragma unroll
    for (int i = 1; i < 8; i++) mx = fmaxf(mx, redmax[i]);

    float sum = 0.f;
    #pragma unroll
    for (int i = 0; i < 4; i++) {
        v[i].x = __expf(v[i].x - mx); v[i].y = __expf(v[i].y - mx);
        v[i].z = __expf(v[i].z - mx); v[i].w = __expf(v[i].w - mx);
        sum += v[i].x + v[i].y + v[i].z + v[i].w;
    }
    #pragma unroll
    for (int o = 16; o > 0; o >>= 1)
        sum += __shfl_xor_sync(0xFFFFFFFFu, sum, o);
    if ((tid & 31) == 0) redsum[tid >> 5] = sum;
    __syncthreads();
    sum = 0.f;
    #pragma unroll
    for (int i = 0; i < 8; i++) sum += redsum[i];

    const float inv = 1.f / sum;
    #pragma unroll
    for (int i = 0; i < 4; i++) {
        __half2 h0 = __floats2half2_rn(v[i].x * inv, v[i].y * inv);
        __half2 h1 = __floats2half2_rn(v[i].z * inv, v[i].w * inv);
        *(__half2*)&q[(tid + i * 256) * 4]     = h0;
        *(__half2*)&q[(tid + i * 256) * 4 + 2] = h1;
    }
}

// ---------------------------------------------------------------------------
extern "C" void kernel_launch(void* const* d_in, const int* in_sizes, int n_in,
                              void* d_out, int out_size)
{
    const float* X  = (const float*)d_in[0];
    const float* WQ = (const float*)d_in[1];
    const float* WK = (const float*)d_in[2];
    const float* WV = (const float*)d_in[3];
    float* out = (float*)d_out;

    __half *Xh, *Qh, *Kh, *VTh, *P, *WTh;
    float *Sc;
    cudaGetSymbolAddress((void**)&Xh,  g_Xh);
    cudaGetSymbolAddress((void**)&Qh,  g_Qh);
    cudaGetSymbolAddress((void**)&Kh,  g_Kh);
    cudaGetSymbolAddress((void**)&VTh, g_VTh);
    cudaGetSymbolAddress((void**)&Sc,  g_S);
    cudaGetSymbolAddress((void**)&P,   g_P);
    cudaGetSymbolAddress((void**)&WTh, g_WTh);
    __half* WQTh = WTh;
    __half* WKTh = WTh + (size_t)D_ * U_;
    __half* WVTh = WTh + 2 * (size_t)D_ * U_;

    const int SMEM_H = 3 * 2 * 128 * 72 * 2;      // 110592 B -> 2 CTAs/SM
    cudaFuncSetAttribute(gemm_f16<true >, cudaFuncAttributeMaxDynamicSharedMemorySize, SMEM_H);
    cudaFuncSetAttribute(gemm_f16<false>, cudaFuncAttributeMaxDynamicSharedMemorySize, SMEM_H);

    const int M = B_ * N_;                        // 16384
    const long long strQ = (long long)N_ * U_;
    const long long strS = (long long)N_ * N_;

    // 1) X -> half; transpose weights -> half
    to_half_kernel<<<(M * D_ / 4 + 255) / 256, 256>>>((const float4*)X, (__half2*)Xh, M * D_ / 4);
    dim3 tb(32, 8), tg(U_ / 32, D_ / 32);
    transpose_half_kernel<<<tg, tb>>>(WQ, WQTh, D_, U_);
    transpose_half_kernel<<<tg, tb>>>(WK, WKTh, D_, U_);
    transpose_half_kernel<<<tg, tb>>>(WV, WVTh, D_, U_);

    // 2) projections (fp16 mma, half out)
    dim3 gP(U_ / 128, M / 128, 1);
    gemm_f16<true><<<gP, 256, SMEM_H>>>(Xh, WQTh, Qh, D_, D_, D_, U_, 0, 0, 0, 1.0f);
    gemm_f16<true><<<gP, 256, SMEM_H>>>(Xh, WKTh, Kh, D_, D_, D_, U_, 0, 0, 0, 1.0f);
    dim3 gV(M / 128, U_ / 128, 1);
    gemm_f16<true><<<gV, 256, SMEM_H>>>(WVTh, Xh, VTh, D_, D_, D_, M, 0, 0, 0, 1.0f);

    // 3) scores: S_b = (1/32) Qh_b @ Kh_b^T
    dim3 gS(N_ / 128, N_ / 128, B_);
    gemm_f16<false><<<gS, 256, SMEM_H>>>(Qh, Kh, Sc, U_, U_, U_, N_,
                                         strQ, strQ, strS, 1.0f / 32.0f);

    // 4) softmax: fp32 scores -> half probs
    softmax_rows_kernel<<<B_ * N_, 256>>>(Sc, P);

    // 5) out_b = P_b @ V_b
    dim3 gO(U_ / 128, N_ / 128, B_);
    gemm_f16<false><<<gO, 256, SMEM_H>>>(P, VTh, out, N_, N_, M, U_,
                                         strS, (long long)N_, strQ, 1.0f);
}